// round 11
// baseline (speedup 1.0000x reference)
#include <cuda_runtime.h>
#include <cuda_fp16.h>
#include <cstdint>

// ---------------------------------------------------------------------------
// HimpNetAlternative: out = scatter_mean( relu(relu(X@W1+b1)@W2+b2), to_index )
// E=320000, C=256, N=10000
//
// Round 11: R10 core (512 thr, 16 warps 4Mx4N, best: 323.7us) + hidden
// phase transition: W2 chunks 0/1 are prefetched into stages 1/2 during
// phase-1 iterations 14/15 (stages provably idle), and phase 2 uses the
// shifted stage map (chunk k -> stage (k+1)%3) so it starts with zero
// prologue stall.
// ---------------------------------------------------------------------------

__device__ __half g_wpack[2][65536];   // W fragments, fp16
__device__ int    g_cnt[16384];

// ------------------------------- helpers ----------------------------------

__device__ __forceinline__ uint32_t smem_u32(const void* p) {
    uint32_t a;
    asm("{ .reg .u64 t; cvta.to.shared.u64 t, %1; cvt.u32.u64 %0, t; }"
        : "=r"(a) : "l"(p));
    return a;
}

__device__ __forceinline__ void cpa16(uint32_t s, const void* g) {
    asm volatile("cp.async.cg.shared.global [%0], [%1], 16;" :: "r"(s), "l"(g));
}

__device__ __forceinline__ void ldmx4(uint32_t* r, uint32_t addr) {
    asm volatile("ldmatrix.sync.aligned.m8n8.x4.shared.b16 {%0,%1,%2,%3}, [%4];"
                 : "=r"(r[0]), "=r"(r[1]), "=r"(r[2]), "=r"(r[3]) : "r"(addr));
}

__device__ __forceinline__ void mma_f16(float* d, const uint32_t* a,
                                        const uint32_t* b) {
    asm volatile(
        "mma.sync.aligned.m16n8k16.row.col.f32.f16.f16.f32 "
        "{%0,%1,%2,%3}, {%4,%5,%6,%7}, {%8,%9}, {%0,%1,%2,%3};"
        : "+f"(d[0]), "+f"(d[1]), "+f"(d[2]), "+f"(d[3])
        : "r"(a[0]), "r"(a[1]), "r"(a[2]), "r"(a[3]), "r"(b[0]), "r"(b[1]));
}

__device__ __forceinline__ uint32_t h2(float x, float y) {
    __half2 h = __floats2half2_rn(x, y);
    return *(uint32_t*)&h;
}

// --------------------------------- prep -----------------------------------
__global__ void prep_kernel(const float* __restrict__ Wa,
                            const float* __restrict__ Wb,
                            __half* __restrict__ dst,
                            float4* __restrict__ out, int n4,
                            int* __restrict__ cnt, int n_nodes) {
    int blk = blockIdx.x;
    if (blk < 512) {
        int o = blk * 256 + threadIdx.x;      // 131072 halves total
        const float* W = (o < 65536) ? Wa : Wb;
        int ol = o & 65535;
        int i    = ol & 3;
        int fp   = (ol >> 2) & 1;
        int lane = (ol >> 3) & 31;
        int f2   = (ol >> 8) & 7;
        int nb   = (ol >> 11) & 1;
        int s    = ol >> 12;
        int f = f2 * 2 + fp;
        int n = nb * 128 + f * 8 + (lane >> 2);
        int k = s * 16 + (lane & 3) * 2 + (i & 1) + (i >> 1) * 8;
        dst[o] = __float2half_rn(W[k * 256 + n]);
    } else {
        int i = (blk - 512) * 256 + threadIdx.x;
        if (i < n4)      out[i] = make_float4(0.f, 0.f, 0.f, 0.f);
        if (i < n_nodes) cnt[i] = 0;
    }
}

__global__ void finalize_kernel(float4* __restrict__ out,
                                const int* __restrict__ cnt, int n4) {
    int i = blockIdx.x * blockDim.x + threadIdx.x;
    if (i >= n4) return;
    int c = cnt[i >> 6];               // 64 float4 per 256-col row
    float4 v = out[i];
    if (c > 0) {
        float inv = 1.0f / (float)c;
        v.x *= inv; v.y *= inv; v.z *= inv; v.w *= inv;
    } else {
        v = make_float4(0.f, 0.f, 0.f, 0.f);
    }
    out[i] = v;
}

// ------------------------------ fused kernel -------------------------------
static constexpr int AF_PITCH = 24;                   // floats
static constexpr int AF_STAGE = 128 * AF_PITCH;       // floats
static constexpr int BS_STAGE = 4096;                 // halves
static constexpr int M1_PITCH = 264;                  // halves
static constexpr size_t SHMEM_BYTES =
    3 * AF_STAGE * 4 + 3 * BS_STAGE * 2 + 128 * M1_PITCH * 2;   // 129024

__global__ void __launch_bounds__(512, 1)
fused_mlp_kernel(const float* __restrict__ X,
                 const __half* __restrict__ Wp1, const __half* __restrict__ Wp2,
                 const float* __restrict__ b1, const float* __restrict__ b2,
                 float* __restrict__ out, const int* __restrict__ ti,
                 int* __restrict__ cnt) {
    extern __shared__ float smem[];
    float*  Af  = smem;
    __half* Bs  = (__half*)(smem + 3 * AF_STAGE);
    __half* M1  = Bs + 3 * BS_STAGE;

    const int tid  = threadIdx.x;
    const int lane = tid & 31, wid = tid >> 5;
    const int wm = wid & 3, wn = wid >> 2;       // 4M x 4N warps, tile 32x64
    const int gid = lane >> 2, tig = lane & 3;
    const int brow = blockIdx.x * 128;

    const float* Asrc = X + (size_t)brow * 256;

    float acc[2][8][4];
#pragma unroll
    for (int m = 0; m < 2; m++)
#pragma unroll
        for (int j = 0; j < 8; j++)
#pragma unroll
            for (int q = 0; q < 4; q++) acc[m][j][q] = 0.0f;

    // loads: one cp.async per thread per tile (512 float4 each)
    const int arow = tid >> 2, ac4 = tid & 3;

    auto loadA = [&](int c, int st) {
        cpa16(smem_u32(&Af[st * AF_STAGE + arow * AF_PITCH + ac4 * 4]),
              Asrc + (size_t)arow * 256 + c * 16 + ac4 * 4);
    };
    auto loadB = [&](const __half* Wp, int c, int st) {
        cpa16(smem_u32(&Bs[st * BS_STAGE + tid * 8]),
              Wp + (size_t)c * 4096 + tid * 8);
    };
    auto loadBfrags = [&](int st, uint32_t (*b)[2]) {
        const __half* bs = &Bs[st * BS_STAGE + wn * 1024];
#pragma unroll
        for (int j2 = 0; j2 < 4; j2++) {
            uint4 v = *(const uint4*)(bs + j2 * 256 + lane * 8);
            b[j2 * 2][0] = v.x;     b[j2 * 2][1] = v.y;
            b[j2 * 2 + 1][0] = v.z; b[j2 * 2 + 1][1] = v.w;
        }
    };

    // ================= phase 1: acc = X @ W1 =================
    loadA(0, 0); loadB(Wp1, 0, 0);
    asm volatile("cp.async.commit_group;" ::: "memory");
    loadA(1, 1); loadB(Wp1, 1, 1);
    asm volatile("cp.async.commit_group;" ::: "memory");

    // hidden under the cp.async fill: histogram + epilogue node prefetch
    if (tid < 128) atomicAdd(&cnt[ti[brow + tid]], 1);
    int nodes[2], nodes8[2];
#pragma unroll
    for (int mf = 0; mf < 2; mf++) {
        const int r = brow + wm * 32 + mf * 16 + gid;
        nodes[mf]  = ti[r];
        nodes8[mf] = ti[r + 8];
    }

    for (int c = 0; c < 16; c++) {
        const int st = c % 3;
        // iter<=14: waits own chunk; iter 15: one W2 group may stay in flight
        asm volatile("cp.async.wait_group 1;" ::: "memory");
        __syncthreads();
        if (c + 2 < 16) {
            const int ls = (c + 2) % 3;
            loadA(c + 2, ls); loadB(Wp1, c + 2, ls);
            asm volatile("cp.async.commit_group;" ::: "memory");
        } else if (c == 14) {
            // stage 1 idle (last read at c=13): prefetch W2 chunk 0
            loadB(Wp2, 0, 1);
            asm volatile("cp.async.commit_group;" ::: "memory");
        } else {           // c == 15
            // stage 2 idle (last read at c=14): prefetch W2 chunk 1
            loadB(Wp2, 1, 2);
            asm volatile("cp.async.commit_group;" ::: "memory");
        }
        const float* as = Af + st * AF_STAGE + wm * 32 * AF_PITCH;
        uint32_t a[2][4];
#pragma unroll
        for (int mf = 0; mf < 2; mf++) {
            const float* ar = as + (mf * 16 + gid) * AF_PITCH + tig * 2;
            float2 v0 = *(const float2*)(ar);
            float2 v1 = *(const float2*)(ar + 8 * AF_PITCH);
            float2 v2 = *(const float2*)(ar + 8);
            float2 v3 = *(const float2*)(ar + 8 * AF_PITCH + 8);
            a[mf][0] = h2(v0.x, v0.y);
            a[mf][1] = h2(v1.x, v1.y);
            a[mf][2] = h2(v2.x, v2.y);
            a[mf][3] = h2(v3.x, v3.y);
        }
        uint32_t b[8][2];
        loadBfrags(st, b);
#pragma unroll
        for (int mf = 0; mf < 2; mf++)
#pragma unroll
            for (int j = 0; j < 8; j++)
                mma_f16(acc[mf][j], a[mf], b[j]);
    }

    // ---- phase 1 epilogue: relu(acc + b1) -> fp16 M1 tile ----
#pragma unroll
    for (int mf = 0; mf < 2; mf++) {
        const int r0 = wm * 32 + mf * 16 + gid, r1 = r0 + 8;
#pragma unroll
        for (int j = 0; j < 8; j++) {
            const int col = wn * 64 + j * 8 + tig * 2;
            float2 bv = *(const float2*)(b1 + col);
            *(uint32_t*)&M1[r0 * M1_PITCH + col] =
                h2(fmaxf(acc[mf][j][0] + bv.x, 0.f),
                   fmaxf(acc[mf][j][1] + bv.y, 0.f));
            *(uint32_t*)&M1[r1 * M1_PITCH + col] =
                h2(fmaxf(acc[mf][j][2] + bv.x, 0.f),
                   fmaxf(acc[mf][j][3] + bv.y, 0.f));
        }
    }

#pragma unroll
    for (int m = 0; m < 2; m++)
#pragma unroll
        for (int j = 0; j < 8; j++)
#pragma unroll
            for (int q = 0; q < 4; q++) acc[m][j][q] = 0.0f;

    // ================= phase 2: M1 @ W2, atomic scatter =================
    // W2 chunk k lives in stage (k+1)%3 (chunks 0/1 prefetched in phase 1).
    const uint32_t m1base = smem_u32(
        &M1[(wm * 32 + (lane & 15)) * M1_PITCH + (lane >> 4) * 8]);

    for (int c = 0; c < 16; c++) {
        const int st = (c + 1) % 3;
        if (c < 15) asm volatile("cp.async.wait_group 1;" ::: "memory");
        else        asm volatile("cp.async.wait_group 0;" ::: "memory");
        __syncthreads();   // iter 0 also publishes M1 to all warps
        if (c + 2 < 16) {
            // target stage (c+3)%3 == c%3, last read at iter c-1: free
            loadB(Wp2, c + 2, c % 3);
            asm volatile("cp.async.commit_group;" ::: "memory");
        }
        uint32_t a[2][4];
#pragma unroll
        for (int mf = 0; mf < 2; mf++)
            ldmx4(a[mf], m1base + (uint32_t)((mf * 16 * M1_PITCH + c * 16) * 2));
        uint32_t b[8][2];
        loadBfrags(st, b);
#pragma unroll
        for (int mf = 0; mf < 2; mf++)
#pragma unroll
            for (int j = 0; j < 8; j++)
                mma_f16(acc[mf][j], a[mf], b[j]);
    }

    // ---- phase 2 epilogue: relu(acc + b2), zero-skipped RED scatter ----
#pragma unroll
    for (int mf = 0; mf < 2; mf++) {
        float* p0 = out + (size_t)nodes[mf]  * 256 + wn * 64 + tig * 2;
        float* p1 = out + (size_t)nodes8[mf] * 256 + wn * 64 + tig * 2;
#pragma unroll
        for (int j = 0; j < 8; j++) {
            const int col = wn * 64 + j * 8 + tig * 2;
            float2 bv = *(const float2*)(b2 + col);
            float v;
            v = acc[mf][j][0] + bv.x; if (v > 0.f) atomicAdd(p0 + j * 8,     v);
            v = acc[mf][j][1] + bv.y; if (v > 0.f) atomicAdd(p0 + j * 8 + 1, v);
            v = acc[mf][j][2] + bv.x; if (v > 0.f) atomicAdd(p1 + j * 8,     v);
            v = acc[mf][j][3] + bv.y; if (v > 0.f) atomicAdd(p1 + j * 8 + 1, v);
        }
    }
}

// ------------------------------ kernel_launch -----------------------------

extern "C" void kernel_launch(void* const* d_in, const int* in_sizes, int n_in,
                              void* d_out, int out_size) {
    const float* X  = (const float*)d_in[0];
    const int*   ti = (const int*)d_in[1];
    int wi = 2;
    if (n_in >= 7 && in_sizes[2] <= 4) wi = 3;
    const float* W1 = (const float*)d_in[wi];
    const float* b1 = (const float*)d_in[wi + 1];
    const float* W2 = (const float*)d_in[wi + 2];
    const float* b2 = (const float*)d_in[wi + 3];

    const int E = in_sizes[1];        // 320000
    const int N = out_size / 256;     // 10000
    float* out = (float*)d_out;

    __half* wp0;  int* cnt;
    cudaGetSymbolAddress((void**)&wp0, g_wpack);
    cudaGetSymbolAddress((void**)&cnt, g_cnt);
    __half* wp1 = wp0 + 65536;

    cudaFuncSetAttribute(fused_mlp_kernel,
                         cudaFuncAttributeMaxDynamicSharedMemorySize,
                         (int)SHMEM_BYTES);

    const int n4 = out_size / 4;
    const int zblocks = (n4 + 255) / 256;
    prep_kernel<<<512 + zblocks, 256>>>(W1, W2, wp0, (float4*)out, n4, cnt, N);

    fused_mlp_kernel<<<E / 128, 512, SHMEM_BYTES>>>(X, wp0, wp1, b1, b2, out,
                                                    ti, cnt);
    finalize_kernel<<<(n4 + 255) / 256, 256>>>((float4*)out, cnt, n4);
}

// round 12
// speedup vs baseline: 1.1508x; 1.1508x over previous
#include <cuda_runtime.h>
#include <cuda_fp16.h>
#include <cstdint>

// ---------------------------------------------------------------------------
// HimpNetAlternative: out = scatter_mean( relu(relu(X@W1+b1)@W2+b2), to_index )
// E=320000, C=256, N=10000
//
// Round 12: R10 core (512 thr, 16 warps 4Mx4N, best: 323.7us) with BK=32:
// 8 K-chunks per phase instead of 16 -> half the barriers/wait_groups.
// Each chunk runs 2 k16 substeps; MMA stream unchanged.
// ---------------------------------------------------------------------------

__device__ __half g_wpack[2][65536];   // W fragments, fp16
__device__ int    g_cnt[16384];

// ------------------------------- helpers ----------------------------------

__device__ __forceinline__ uint32_t smem_u32(const void* p) {
    uint32_t a;
    asm("{ .reg .u64 t; cvta.to.shared.u64 t, %1; cvt.u32.u64 %0, t; }"
        : "=r"(a) : "l"(p));
    return a;
}

__device__ __forceinline__ void cpa16(uint32_t s, const void* g) {
    asm volatile("cp.async.cg.shared.global [%0], [%1], 16;" :: "r"(s), "l"(g));
}

__device__ __forceinline__ void ldmx4(uint32_t* r, uint32_t addr) {
    asm volatile("ldmatrix.sync.aligned.m8n8.x4.shared.b16 {%0,%1,%2,%3}, [%4];"
                 : "=r"(r[0]), "=r"(r[1]), "=r"(r[2]), "=r"(r[3]) : "r"(addr));
}

__device__ __forceinline__ void mma_f16(float* d, const uint32_t* a,
                                        const uint32_t* b) {
    asm volatile(
        "mma.sync.aligned.m16n8k16.row.col.f32.f16.f16.f32 "
        "{%0,%1,%2,%3}, {%4,%5,%6,%7}, {%8,%9}, {%0,%1,%2,%3};"
        : "+f"(d[0]), "+f"(d[1]), "+f"(d[2]), "+f"(d[3])
        : "r"(a[0]), "r"(a[1]), "r"(a[2]), "r"(a[3]), "r"(b[0]), "r"(b[1]));
}

__device__ __forceinline__ uint32_t h2(float x, float y) {
    __half2 h = __floats2half2_rn(x, y);
    return *(uint32_t*)&h;
}

// --------------------------------- prep -----------------------------------
__global__ void prep_kernel(const float* __restrict__ Wa,
                            const float* __restrict__ Wb,
                            __half* __restrict__ dst,
                            float4* __restrict__ out, int n4,
                            int* __restrict__ cnt, int n_nodes) {
    int blk = blockIdx.x;
    if (blk < 512) {
        int o = blk * 256 + threadIdx.x;      // 131072 halves total
        const float* W = (o < 65536) ? Wa : Wb;
        int ol = o & 65535;
        int i    = ol & 3;
        int fp   = (ol >> 2) & 1;
        int lane = (ol >> 3) & 31;
        int f2   = (ol >> 8) & 7;
        int nb   = (ol >> 11) & 1;
        int s    = ol >> 12;
        int f = f2 * 2 + fp;
        int n = nb * 128 + f * 8 + (lane >> 2);
        int k = s * 16 + (lane & 3) * 2 + (i & 1) + (i >> 1) * 8;
        dst[o] = __float2half_rn(W[k * 256 + n]);
    } else {
        int i = (blk - 512) * 256 + threadIdx.x;
        if (i < n4)      out[i] = make_float4(0.f, 0.f, 0.f, 0.f);
        if (i < n_nodes) cnt[i] = 0;
    }
}

__global__ void finalize_kernel(float4* __restrict__ out,
                                const int* __restrict__ cnt, int n4) {
    int i = blockIdx.x * blockDim.x + threadIdx.x;
    if (i >= n4) return;
    int c = cnt[i >> 6];               // 64 float4 per 256-col row
    float4 v = out[i];
    if (c > 0) {
        float inv = 1.0f / (float)c;
        v.x *= inv; v.y *= inv; v.z *= inv; v.w *= inv;
    } else {
        v = make_float4(0.f, 0.f, 0.f, 0.f);
    }
    out[i] = v;
}

// ------------------------------ fused kernel -------------------------------
static constexpr int AF_PITCH = 40;                   // floats (32 data + 8 pad)
static constexpr int AF_STAGE = 128 * AF_PITCH;       // 5120 floats
static constexpr int BS_STAGE = 8192;                 // halves (32k x 256n)
static constexpr int M1_PITCH = 264;                  // halves
static constexpr size_t SHMEM_BYTES =
    3 * AF_STAGE * 4 + 3 * BS_STAGE * 2 + 128 * M1_PITCH * 2;   // 178176

__global__ void __launch_bounds__(512, 1)
fused_mlp_kernel(const float* __restrict__ X,
                 const __half* __restrict__ Wp1, const __half* __restrict__ Wp2,
                 const float* __restrict__ b1, const float* __restrict__ b2,
                 float* __restrict__ out, const int* __restrict__ ti,
                 int* __restrict__ cnt) {
    extern __shared__ float smem[];
    float*  Af  = smem;
    __half* Bs  = (__half*)(smem + 3 * AF_STAGE);
    __half* M1  = Bs + 3 * BS_STAGE;

    const int tid  = threadIdx.x;
    const int lane = tid & 31, wid = tid >> 5;
    const int wm = wid & 3, wn = wid >> 2;       // 4M x 4N warps, tile 32x64
    const int gid = lane >> 2, tig = lane & 3;
    const int brow = blockIdx.x * 128;

    const float* Asrc = X + (size_t)brow * 256;

    float acc[2][8][4];
#pragma unroll
    for (int m = 0; m < 2; m++)
#pragma unroll
        for (int j = 0; j < 8; j++)
#pragma unroll
            for (int q = 0; q < 4; q++) acc[m][j][q] = 0.0f;

    // A: 128 rows x 32 floats per chunk = 1024 float4; 2 per thread
    const int arow = tid >> 2;

    auto loadA = [&](int c, int st) {
#pragma unroll
        for (int i = 0; i < 2; i++) {
            int c4 = (tid & 3) + i * 4;         // 0..7
            cpa16(smem_u32(&Af[st * AF_STAGE + arow * AF_PITCH + c4 * 4]),
                  Asrc + (size_t)arow * 256 + c * 32 + c4 * 4);
        }
    };
    // B: 32k x 256n halves per chunk = 1024 x 16B; 2 per thread
    auto loadB = [&](const __half* Wp, int c, int st) {
#pragma unroll
        for (int i = 0; i < 2; i++) {
            int f = tid + i * 512;
            cpa16(smem_u32(&Bs[st * BS_STAGE + f * 8]),
                  Wp + (size_t)c * 8192 + f * 8);
        }
    };
    auto loadBfrags = [&](int st, int sl, uint32_t (*b)[2]) {
        const __half* bs = &Bs[st * BS_STAGE + sl * 4096 + wn * 1024];
#pragma unroll
        for (int j2 = 0; j2 < 4; j2++) {
            uint4 v = *(const uint4*)(bs + j2 * 256 + lane * 8);
            b[j2 * 2][0] = v.x;     b[j2 * 2][1] = v.y;
            b[j2 * 2 + 1][0] = v.z; b[j2 * 2 + 1][1] = v.w;
        }
    };

    // ================= phase 1: acc = X @ W1 =================
    loadA(0, 0); loadB(Wp1, 0, 0);
    asm volatile("cp.async.commit_group;" ::: "memory");
    loadA(1, 1); loadB(Wp1, 1, 1);
    asm volatile("cp.async.commit_group;" ::: "memory");

    // hidden under the cp.async fill: histogram + epilogue node prefetch
    if (tid < 128) atomicAdd(&cnt[ti[brow + tid]], 1);
    int nodes[2], nodes8[2];
#pragma unroll
    for (int mf = 0; mf < 2; mf++) {
        const int r = brow + wm * 32 + mf * 16 + gid;
        nodes[mf]  = ti[r];
        nodes8[mf] = ti[r + 8];
    }

    for (int c = 0; c < 8; c++) {
        const int st = c % 3;
        if (c < 7) asm volatile("cp.async.wait_group 1;" ::: "memory");
        else       asm volatile("cp.async.wait_group 0;" ::: "memory");
        __syncthreads();
        if (c + 2 < 8) {
            const int ls = (c + 2) % 3;
            loadA(c + 2, ls); loadB(Wp1, c + 2, ls);
            asm volatile("cp.async.commit_group;" ::: "memory");
        }
#pragma unroll
        for (int sl = 0; sl < 2; sl++) {
            const float* as = Af + st * AF_STAGE + wm * 32 * AF_PITCH + sl * 16;
            uint32_t a[2][4];
#pragma unroll
            for (int mf = 0; mf < 2; mf++) {
                const float* ar = as + (mf * 16 + gid) * AF_PITCH + tig * 2;
                float2 v0 = *(const float2*)(ar);
                float2 v1 = *(const float2*)(ar + 8 * AF_PITCH);
                float2 v2 = *(const float2*)(ar + 8);
                float2 v3 = *(const float2*)(ar + 8 * AF_PITCH + 8);
                a[mf][0] = h2(v0.x, v0.y);
                a[mf][1] = h2(v1.x, v1.y);
                a[mf][2] = h2(v2.x, v2.y);
                a[mf][3] = h2(v3.x, v3.y);
            }
            uint32_t b[8][2];
            loadBfrags(st, sl, b);
#pragma unroll
            for (int mf = 0; mf < 2; mf++)
#pragma unroll
                for (int j = 0; j < 8; j++)
                    mma_f16(acc[mf][j], a[mf], b[j]);
        }
    }
    __syncthreads();   // all warps done with B stages before phase-2 prefetch

    // ---- phase 1 epilogue: relu(acc + b1) -> fp16 M1 tile ----
#pragma unroll
    for (int mf = 0; mf < 2; mf++) {
        const int r0 = wm * 32 + mf * 16 + gid, r1 = r0 + 8;
#pragma unroll
        for (int j = 0; j < 8; j++) {
            const int col = wn * 64 + j * 8 + tig * 2;
            float2 bv = *(const float2*)(b1 + col);
            *(uint32_t*)&M1[r0 * M1_PITCH + col] =
                h2(fmaxf(acc[mf][j][0] + bv.x, 0.f),
                   fmaxf(acc[mf][j][1] + bv.y, 0.f));
            *(uint32_t*)&M1[r1 * M1_PITCH + col] =
                h2(fmaxf(acc[mf][j][2] + bv.x, 0.f),
                   fmaxf(acc[mf][j][3] + bv.y, 0.f));
        }
    }

#pragma unroll
    for (int m = 0; m < 2; m++)
#pragma unroll
        for (int j = 0; j < 8; j++)
#pragma unroll
            for (int q = 0; q < 4; q++) acc[m][j][q] = 0.0f;

    // ================= phase 2: M1 @ W2, atomic scatter =================
    loadB(Wp2, 0, 0);
    asm volatile("cp.async.commit_group;" ::: "memory");
    loadB(Wp2, 1, 1);
    asm volatile("cp.async.commit_group;" ::: "memory");

    const uint32_t m1base = smem_u32(
        &M1[(wm * 32 + (lane & 15)) * M1_PITCH + (lane >> 4) * 8]);

    for (int c = 0; c < 8; c++) {
        const int st = c % 3;
        if (c < 7) asm volatile("cp.async.wait_group 1;" ::: "memory");
        else       asm volatile("cp.async.wait_group 0;" ::: "memory");
        __syncthreads();   // iter 0 also publishes M1 to all warps
        if (c + 2 < 8) {
            loadB(Wp2, c + 2, (c + 2) % 3);
            asm volatile("cp.async.commit_group;" ::: "memory");
        }
#pragma unroll
        for (int sl = 0; sl < 2; sl++) {
            uint32_t a[2][4];
#pragma unroll
            for (int mf = 0; mf < 2; mf++)
                ldmx4(a[mf], m1base +
                      (uint32_t)((mf * 16 * M1_PITCH + c * 32 + sl * 16) * 2));
            uint32_t b[8][2];
            loadBfrags(st, sl, b);
#pragma unroll
            for (int mf = 0; mf < 2; mf++)
#pragma unroll
                for (int j = 0; j < 8; j++)
                    mma_f16(acc[mf][j], a[mf], b[j]);
        }
    }

    // ---- phase 2 epilogue: relu(acc + b2), zero-skipped RED scatter ----
#pragma unroll
    for (int mf = 0; mf < 2; mf++) {
        float* p0 = out + (size_t)nodes[mf]  * 256 + wn * 64 + tig * 2;
        float* p1 = out + (size_t)nodes8[mf] * 256 + wn * 64 + tig * 2;
#pragma unroll
        for (int j = 0; j < 8; j++) {
            const int col = wn * 64 + j * 8 + tig * 2;
            float2 bv = *(const float2*)(b2 + col);
            float v;
            v = acc[mf][j][0] + bv.x; if (v > 0.f) atomicAdd(p0 + j * 8,     v);
            v = acc[mf][j][1] + bv.y; if (v > 0.f) atomicAdd(p0 + j * 8 + 1, v);
            v = acc[mf][j][2] + bv.x; if (v > 0.f) atomicAdd(p1 + j * 8,     v);
            v = acc[mf][j][3] + bv.y; if (v > 0.f) atomicAdd(p1 + j * 8 + 1, v);
        }
    }
}

// ------------------------------ kernel_launch -----------------------------

extern "C" void kernel_launch(void* const* d_in, const int* in_sizes, int n_in,
                              void* d_out, int out_size) {
    const float* X  = (const float*)d_in[0];
    const int*   ti = (const int*)d_in[1];
    int wi = 2;
    if (n_in >= 7 && in_sizes[2] <= 4) wi = 3;
    const float* W1 = (const float*)d_in[wi];
    const float* b1 = (const float*)d_in[wi + 1];
    const float* W2 = (const float*)d_in[wi + 2];
    const float* b2 = (const float*)d_in[wi + 3];

    const int E = in_sizes[1];        // 320000
    const int N = out_size / 256;     // 10000
    float* out = (float*)d_out;

    __half* wp0;  int* cnt;
    cudaGetSymbolAddress((void**)&wp0, g_wpack);
    cudaGetSymbolAddress((void**)&cnt, g_cnt);
    __half* wp1 = wp0 + 65536;

    cudaFuncSetAttribute(fused_mlp_kernel,
                         cudaFuncAttributeMaxDynamicSharedMemorySize,
                         (int)SHMEM_BYTES);

    const int n4 = out_size / 4;
    const int zblocks = (n4 + 255) / 256;
    prep_kernel<<<512 + zblocks, 256>>>(W1, W2, wp0, (float4*)out, n4, cnt, N);

    fused_mlp_kernel<<<E / 128, 512, SHMEM_BYTES>>>(X, wp0, wp1, b1, b2, out,
                                                    ti, cnt);
    finalize_kernel<<<(n4 + 255) / 256, 256>>>((float4*)out, cnt, n4);
}

// round 13
// speedup vs baseline: 1.2546x; 1.0902x over previous
#include <cuda_runtime.h>
#include <cuda_fp16.h>
#include <cstdint>

// ---------------------------------------------------------------------------
// HimpNetAlternative: out = scatter_mean( relu(relu(X@W1+b1)@W2+b2), to_index )
// E=320000, C=256, N=10000
//
// Round 13: R12 core (BK=32, 512 thr, 16 warps 4Mx4N, best: 317.5us) +
//   - 4-stage cp.async pipeline (loads 3 chunks ahead; 215KB smem)
//   - epilogue scatter via red.global.add.v2.f32 (half the RED instructions)
// ---------------------------------------------------------------------------

__device__ __half g_wpack[2][65536];   // W fragments, fp16
__device__ int    g_cnt[16384];

// ------------------------------- helpers ----------------------------------

__device__ __forceinline__ uint32_t smem_u32(const void* p) {
    uint32_t a;
    asm("{ .reg .u64 t; cvta.to.shared.u64 t, %1; cvt.u32.u64 %0, t; }"
        : "=r"(a) : "l"(p));
    return a;
}

__device__ __forceinline__ void cpa16(uint32_t s, const void* g) {
    asm volatile("cp.async.cg.shared.global [%0], [%1], 16;" :: "r"(s), "l"(g));
}

__device__ __forceinline__ void ldmx4(uint32_t* r, uint32_t addr) {
    asm volatile("ldmatrix.sync.aligned.m8n8.x4.shared.b16 {%0,%1,%2,%3}, [%4];"
                 : "=r"(r[0]), "=r"(r[1]), "=r"(r[2]), "=r"(r[3]) : "r"(addr));
}

__device__ __forceinline__ void mma_f16(float* d, const uint32_t* a,
                                        const uint32_t* b) {
    asm volatile(
        "mma.sync.aligned.m16n8k16.row.col.f32.f16.f16.f32 "
        "{%0,%1,%2,%3}, {%4,%5,%6,%7}, {%8,%9}, {%0,%1,%2,%3};"
        : "+f"(d[0]), "+f"(d[1]), "+f"(d[2]), "+f"(d[3])
        : "r"(a[0]), "r"(a[1]), "r"(a[2]), "r"(a[3]), "r"(b[0]), "r"(b[1]));
}

__device__ __forceinline__ uint32_t h2(float x, float y) {
    __half2 h = __floats2half2_rn(x, y);
    return *(uint32_t*)&h;
}

__device__ __forceinline__ void red_v2(float* p, float x, float y) {
    asm volatile("red.global.add.v2.f32 [%0], {%1, %2};"
                 :: "l"(p), "f"(x), "f"(y) : "memory");
}

// --------------------------------- prep -----------------------------------
__global__ void prep_kernel(const float* __restrict__ Wa,
                            const float* __restrict__ Wb,
                            __half* __restrict__ dst,
                            float4* __restrict__ out, int n4,
                            int* __restrict__ cnt, int n_nodes) {
    int blk = blockIdx.x;
    if (blk < 512) {
        int o = blk * 256 + threadIdx.x;      // 131072 halves total
        const float* W = (o < 65536) ? Wa : Wb;
        int ol = o & 65535;
        int i    = ol & 3;
        int fp   = (ol >> 2) & 1;
        int lane = (ol >> 3) & 31;
        int f2   = (ol >> 8) & 7;
        int nb   = (ol >> 11) & 1;
        int s    = ol >> 12;
        int f = f2 * 2 + fp;
        int n = nb * 128 + f * 8 + (lane >> 2);
        int k = s * 16 + (lane & 3) * 2 + (i & 1) + (i >> 1) * 8;
        dst[o] = __float2half_rn(W[k * 256 + n]);
    } else {
        int i = (blk - 512) * 256 + threadIdx.x;
        if (i < n4)      out[i] = make_float4(0.f, 0.f, 0.f, 0.f);
        if (i < n_nodes) cnt[i] = 0;
    }
}

__global__ void finalize_kernel(float4* __restrict__ out,
                                const int* __restrict__ cnt, int n4) {
    int i = blockIdx.x * blockDim.x + threadIdx.x;
    if (i >= n4) return;
    int c = cnt[i >> 6];               // 64 float4 per 256-col row
    float4 v = out[i];
    if (c > 0) {
        float inv = 1.0f / (float)c;
        v.x *= inv; v.y *= inv; v.z *= inv; v.w *= inv;
    } else {
        v = make_float4(0.f, 0.f, 0.f, 0.f);
    }
    out[i] = v;
}

// ------------------------------ fused kernel -------------------------------
static constexpr int NSTAGE = 4;
static constexpr int AF_PITCH = 40;                   // floats (32 data + 8 pad)
static constexpr int AF_STAGE = 128 * AF_PITCH;       // 5120 floats
static constexpr int BS_STAGE = 8192;                 // halves (32k x 256n)
static constexpr int M1_PITCH = 264;                  // halves
static constexpr size_t SHMEM_BYTES =
    NSTAGE * AF_STAGE * 4 + NSTAGE * BS_STAGE * 2 + 128 * M1_PITCH * 2; // 215040

__global__ void __launch_bounds__(512, 1)
fused_mlp_kernel(const float* __restrict__ X,
                 const __half* __restrict__ Wp1, const __half* __restrict__ Wp2,
                 const float* __restrict__ b1, const float* __restrict__ b2,
                 float* __restrict__ out, const int* __restrict__ ti,
                 int* __restrict__ cnt) {
    extern __shared__ float smem[];
    float*  Af  = smem;
    __half* Bs  = (__half*)(smem + NSTAGE * AF_STAGE);
    __half* M1  = Bs + NSTAGE * BS_STAGE;

    const int tid  = threadIdx.x;
    const int lane = tid & 31, wid = tid >> 5;
    const int wm = wid & 3, wn = wid >> 2;       // 4M x 4N warps, tile 32x64
    const int gid = lane >> 2, tig = lane & 3;
    const int brow = blockIdx.x * 128;

    const float* Asrc = X + (size_t)brow * 256;

    float acc[2][8][4];
#pragma unroll
    for (int m = 0; m < 2; m++)
#pragma unroll
        for (int j = 0; j < 8; j++)
#pragma unroll
            for (int q = 0; q < 4; q++) acc[m][j][q] = 0.0f;

    // A: 128 rows x 32 floats per chunk = 1024 float4; 2 per thread
    const int arow = tid >> 2;

    auto loadA = [&](int c, int st) {
#pragma unroll
        for (int i = 0; i < 2; i++) {
            int c4 = (tid & 3) + i * 4;         // 0..7
            cpa16(smem_u32(&Af[st * AF_STAGE + arow * AF_PITCH + c4 * 4]),
                  Asrc + (size_t)arow * 256 + c * 32 + c4 * 4);
        }
    };
    // B: 32k x 256n halves per chunk = 1024 x 16B; 2 per thread
    auto loadB = [&](const __half* Wp, int c, int st) {
#pragma unroll
        for (int i = 0; i < 2; i++) {
            int f = tid + i * 512;
            cpa16(smem_u32(&Bs[st * BS_STAGE + f * 8]),
                  Wp + (size_t)c * 8192 + f * 8);
        }
    };
    auto loadBfrags = [&](int st, int sl, uint32_t (*b)[2]) {
        const __half* bs = &Bs[st * BS_STAGE + sl * 4096 + wn * 1024];
#pragma unroll
        for (int j2 = 0; j2 < 4; j2++) {
            uint4 v = *(const uint4*)(bs + j2 * 256 + lane * 8);
            b[j2 * 2][0] = v.x;     b[j2 * 2][1] = v.y;
            b[j2 * 2 + 1][0] = v.z; b[j2 * 2 + 1][1] = v.w;
        }
    };

    // ================= phase 1: acc = X @ W1 =================
    loadA(0, 0); loadB(Wp1, 0, 0);
    asm volatile("cp.async.commit_group;" ::: "memory");
    loadA(1, 1); loadB(Wp1, 1, 1);
    asm volatile("cp.async.commit_group;" ::: "memory");
    loadA(2, 2); loadB(Wp1, 2, 2);
    asm volatile("cp.async.commit_group;" ::: "memory");

    // hidden under the cp.async fill: histogram + epilogue node prefetch
    if (tid < 128) atomicAdd(&cnt[ti[brow + tid]], 1);
    int nodes[2], nodes8[2];
#pragma unroll
    for (int mf = 0; mf < 2; mf++) {
        const int r = brow + wm * 32 + mf * 16 + gid;
        nodes[mf]  = ti[r];
        nodes8[mf] = ti[r + 8];
    }

#pragma unroll
    for (int c = 0; c < 8; c++) {
        const int st = c & 3;
        if (c < 6)      asm volatile("cp.async.wait_group 2;" ::: "memory");
        else if (c == 6) asm volatile("cp.async.wait_group 1;" ::: "memory");
        else             asm volatile("cp.async.wait_group 0;" ::: "memory");
        __syncthreads();
        if (c + 3 < 8) {
            const int ls = (c + 3) & 3;
            loadA(c + 3, ls); loadB(Wp1, c + 3, ls);
            asm volatile("cp.async.commit_group;" ::: "memory");
        }
#pragma unroll
        for (int sl = 0; sl < 2; sl++) {
            const float* as = Af + st * AF_STAGE + wm * 32 * AF_PITCH + sl * 16;
            uint32_t a[2][4];
#pragma unroll
            for (int mf = 0; mf < 2; mf++) {
                const float* ar = as + (mf * 16 + gid) * AF_PITCH + tig * 2;
                float2 v0 = *(const float2*)(ar);
                float2 v1 = *(const float2*)(ar + 8 * AF_PITCH);
                float2 v2 = *(const float2*)(ar + 8);
                float2 v3 = *(const float2*)(ar + 8 * AF_PITCH + 8);
                a[mf][0] = h2(v0.x, v0.y);
                a[mf][1] = h2(v1.x, v1.y);
                a[mf][2] = h2(v2.x, v2.y);
                a[mf][3] = h2(v3.x, v3.y);
            }
            uint32_t b[8][2];
            loadBfrags(st, sl, b);
#pragma unroll
            for (int mf = 0; mf < 2; mf++)
#pragma unroll
                for (int j = 0; j < 8; j++)
                    mma_f16(acc[mf][j], a[mf], b[j]);
        }
    }
    __syncthreads();   // all warps done with A/B stages before phase-2 prefetch

    // ---- phase 1 epilogue: relu(acc + b1) -> fp16 M1 tile ----
#pragma unroll
    for (int mf = 0; mf < 2; mf++) {
        const int r0 = wm * 32 + mf * 16 + gid, r1 = r0 + 8;
#pragma unroll
        for (int j = 0; j < 8; j++) {
            const int col = wn * 64 + j * 8 + tig * 2;
            float2 bv = *(const float2*)(b1 + col);
            *(uint32_t*)&M1[r0 * M1_PITCH + col] =
                h2(fmaxf(acc[mf][j][0] + bv.x, 0.f),
                   fmaxf(acc[mf][j][1] + bv.y, 0.f));
            *(uint32_t*)&M1[r1 * M1_PITCH + col] =
                h2(fmaxf(acc[mf][j][2] + bv.x, 0.f),
                   fmaxf(acc[mf][j][3] + bv.y, 0.f));
        }
    }

#pragma unroll
    for (int m = 0; m < 2; m++)
#pragma unroll
        for (int j = 0; j < 8; j++)
#pragma unroll
            for (int q = 0; q < 4; q++) acc[m][j][q] = 0.0f;

    // ================= phase 2: M1 @ W2, atomic scatter =================
    loadB(Wp2, 0, 0);
    asm volatile("cp.async.commit_group;" ::: "memory");
    loadB(Wp2, 1, 1);
    asm volatile("cp.async.commit_group;" ::: "memory");
    loadB(Wp2, 2, 2);
    asm volatile("cp.async.commit_group;" ::: "memory");

    const uint32_t m1base = smem_u32(
        &M1[(wm * 32 + (lane & 15)) * M1_PITCH + (lane >> 4) * 8]);

#pragma unroll
    for (int c = 0; c < 8; c++) {
        const int st = c & 3;
        if (c < 6)      asm volatile("cp.async.wait_group 2;" ::: "memory");
        else if (c == 6) asm volatile("cp.async.wait_group 1;" ::: "memory");
        else             asm volatile("cp.async.wait_group 0;" ::: "memory");
        __syncthreads();   // iter 0 also publishes M1 to all warps
        if (c + 3 < 8) {
            loadB(Wp2, c + 3, (c + 3) & 3);
            asm volatile("cp.async.commit_group;" ::: "memory");
        }
#pragma unroll
        for (int sl = 0; sl < 2; sl++) {
            uint32_t a[2][4];
#pragma unroll
            for (int mf = 0; mf < 2; mf++)
                ldmx4(a[mf], m1base +
                      (uint32_t)((mf * 16 * M1_PITCH + c * 32 + sl * 16) * 2));
            uint32_t b[8][2];
            loadBfrags(st, sl, b);
#pragma unroll
            for (int mf = 0; mf < 2; mf++)
#pragma unroll
                for (int j = 0; j < 8; j++)
                    mma_f16(acc[mf][j], a[mf], b[j]);
        }
    }

    // ---- phase 2 epilogue: relu(acc + b2), zero-skipped RED.v2 scatter ----
#pragma unroll
    for (int mf = 0; mf < 2; mf++) {
        float* p0 = out + (size_t)nodes[mf]  * 256 + wn * 64 + tig * 2;
        float* p1 = out + (size_t)nodes8[mf] * 256 + wn * 64 + tig * 2;
#pragma unroll
        for (int j = 0; j < 8; j++) {
            const int col = wn * 64 + j * 8 + tig * 2;
            float2 bv = *(const float2*)(b2 + col);
            float vx, vy;
            vx = fmaxf(acc[mf][j][0] + bv.x, 0.f);
            vy = fmaxf(acc[mf][j][1] + bv.y, 0.f);
            if (vx > 0.f || vy > 0.f) red_v2(p0 + j * 8, vx, vy);
            vx = fmaxf(acc[mf][j][2] + bv.x, 0.f);
            vy = fmaxf(acc[mf][j][3] + bv.y, 0.f);
            if (vx > 0.f || vy > 0.f) red_v2(p1 + j * 8, vx, vy);
        }
    }
}

// ------------------------------ kernel_launch -----------------------------

extern "C" void kernel_launch(void* const* d_in, const int* in_sizes, int n_in,
                              void* d_out, int out_size) {
    const float* X  = (const float*)d_in[0];
    const int*   ti = (const int*)d_in[1];
    int wi = 2;
    if (n_in >= 7 && in_sizes[2] <= 4) wi = 3;
    const float* W1 = (const float*)d_in[wi];
    const float* b1 = (const float*)d_in[wi + 1];
    const float* W2 = (const float*)d_in[wi + 2];
    const float* b2 = (const float*)d_in[wi + 3];

    const int E = in_sizes[1];        // 320000
    const int N = out_size / 256;     // 10000
    float* out = (float*)d_out;

    __half* wp0;  int* cnt;
    cudaGetSymbolAddress((void**)&wp0, g_wpack);
    cudaGetSymbolAddress((void**)&cnt, g_cnt);
    __half* wp1 = wp0 + 65536;

    cudaFuncSetAttribute(fused_mlp_kernel,
                         cudaFuncAttributeMaxDynamicSharedMemorySize,
                         (int)SHMEM_BYTES);

    const int n4 = out_size / 4;
    const int zblocks = (n4 + 255) / 256;
    prep_kernel<<<512 + zblocks, 256>>>(W1, W2, wp0, (float4*)out, n4, cnt, N);

    fused_mlp_kernel<<<E / 128, 512, SHMEM_BYTES>>>(X, wp0, wp1, b1, b2, out,
                                                    ti, cnt);
    finalize_kernel<<<(n4 + 255) / 256, 256>>>((float4*)out, cnt, n4);
}

// round 14
// speedup vs baseline: 1.2674x; 1.0102x over previous
#include <cuda_runtime.h>
#include <cuda_fp16.h>
#include <cstdint>

// ---------------------------------------------------------------------------
// HimpNetAlternative: out = scatter_mean( relu(relu(X@W1+b1)@W2+b2), to_index )
// E=320000, C=256, N=10000
//
// Round 14: R13 core (4-stage BK=32, 512 thr, v2 REDs, best: 291.2us) +
// W2 chunks 0..2 prefetched during phase-1 iterations 5..7 into the stages
// freed by those iterations (compile-time selected: the c-loop is fully
// unrolled, unlike R11's runtime-branch version). Phase 2 starts hot.
// ---------------------------------------------------------------------------

__device__ __half g_wpack[2][65536];   // W fragments, fp16
__device__ int    g_cnt[16384];

// ------------------------------- helpers ----------------------------------

__device__ __forceinline__ uint32_t smem_u32(const void* p) {
    uint32_t a;
    asm("{ .reg .u64 t; cvta.to.shared.u64 t, %1; cvt.u32.u64 %0, t; }"
        : "=r"(a) : "l"(p));
    return a;
}

__device__ __forceinline__ void cpa16(uint32_t s, const void* g) {
    asm volatile("cp.async.cg.shared.global [%0], [%1], 16;" :: "r"(s), "l"(g));
}

__device__ __forceinline__ void ldmx4(uint32_t* r, uint32_t addr) {
    asm volatile("ldmatrix.sync.aligned.m8n8.x4.shared.b16 {%0,%1,%2,%3}, [%4];"
                 : "=r"(r[0]), "=r"(r[1]), "=r"(r[2]), "=r"(r[3]) : "r"(addr));
}

__device__ __forceinline__ void mma_f16(float* d, const uint32_t* a,
                                        const uint32_t* b) {
    asm volatile(
        "mma.sync.aligned.m16n8k16.row.col.f32.f16.f16.f32 "
        "{%0,%1,%2,%3}, {%4,%5,%6,%7}, {%8,%9}, {%0,%1,%2,%3};"
        : "+f"(d[0]), "+f"(d[1]), "+f"(d[2]), "+f"(d[3])
        : "r"(a[0]), "r"(a[1]), "r"(a[2]), "r"(a[3]), "r"(b[0]), "r"(b[1]));
}

__device__ __forceinline__ uint32_t h2(float x, float y) {
    __half2 h = __floats2half2_rn(x, y);
    return *(uint32_t*)&h;
}

__device__ __forceinline__ void red_v2(float* p, float x, float y) {
    asm volatile("red.global.add.v2.f32 [%0], {%1, %2};"
                 :: "l"(p), "f"(x), "f"(y) : "memory");
}

// --------------------------------- prep -----------------------------------
__global__ void prep_kernel(const float* __restrict__ Wa,
                            const float* __restrict__ Wb,
                            __half* __restrict__ dst,
                            float4* __restrict__ out, int n4,
                            int* __restrict__ cnt, int n_nodes) {
    int blk = blockIdx.x;
    if (blk < 512) {
        int o = blk * 256 + threadIdx.x;      // 131072 halves total
        const float* W = (o < 65536) ? Wa : Wb;
        int ol = o & 65535;
        int i    = ol & 3;
        int fp   = (ol >> 2) & 1;
        int lane = (ol >> 3) & 31;
        int f2   = (ol >> 8) & 7;
        int nb   = (ol >> 11) & 1;
        int s    = ol >> 12;
        int f = f2 * 2 + fp;
        int n = nb * 128 + f * 8 + (lane >> 2);
        int k = s * 16 + (lane & 3) * 2 + (i & 1) + (i >> 1) * 8;
        dst[o] = __float2half_rn(W[k * 256 + n]);
    } else {
        int i = (blk - 512) * 256 + threadIdx.x;
        if (i < n4)      out[i] = make_float4(0.f, 0.f, 0.f, 0.f);
        if (i < n_nodes) cnt[i] = 0;
    }
}

__global__ void finalize_kernel(float4* __restrict__ out,
                                const int* __restrict__ cnt, int n4) {
    int i = blockIdx.x * blockDim.x + threadIdx.x;
    if (i >= n4) return;
    int c = cnt[i >> 6];               // 64 float4 per 256-col row
    float4 v = out[i];
    if (c > 0) {
        float inv = 1.0f / (float)c;
        v.x *= inv; v.y *= inv; v.z *= inv; v.w *= inv;
    } else {
        v = make_float4(0.f, 0.f, 0.f, 0.f);
    }
    out[i] = v;
}

// ------------------------------ fused kernel -------------------------------
static constexpr int NSTAGE = 4;
static constexpr int AF_PITCH = 40;                   // floats (32 data + 8 pad)
static constexpr int AF_STAGE = 128 * AF_PITCH;       // 5120 floats
static constexpr int BS_STAGE = 8192;                 // halves (32k x 256n)
static constexpr int M1_PITCH = 264;                  // halves
static constexpr size_t SHMEM_BYTES =
    NSTAGE * AF_STAGE * 4 + NSTAGE * BS_STAGE * 2 + 128 * M1_PITCH * 2; // 215040

__global__ void __launch_bounds__(512, 1)
fused_mlp_kernel(const float* __restrict__ X,
                 const __half* __restrict__ Wp1, const __half* __restrict__ Wp2,
                 const float* __restrict__ b1, const float* __restrict__ b2,
                 float* __restrict__ out, const int* __restrict__ ti,
                 int* __restrict__ cnt) {
    extern __shared__ float smem[];
    float*  Af  = smem;
    __half* Bs  = (__half*)(smem + NSTAGE * AF_STAGE);
    __half* M1  = Bs + NSTAGE * BS_STAGE;

    const int tid  = threadIdx.x;
    const int lane = tid & 31, wid = tid >> 5;
    const int wm = wid & 3, wn = wid >> 2;       // 4M x 4N warps, tile 32x64
    const int gid = lane >> 2, tig = lane & 3;
    const int brow = blockIdx.x * 128;

    const float* Asrc = X + (size_t)brow * 256;

    float acc[2][8][4];
#pragma unroll
    for (int m = 0; m < 2; m++)
#pragma unroll
        for (int j = 0; j < 8; j++)
#pragma unroll
            for (int q = 0; q < 4; q++) acc[m][j][q] = 0.0f;

    // A: 128 rows x 32 floats per chunk = 1024 float4; 2 per thread
    const int arow = tid >> 2;

    auto loadA = [&](int c, int st) {
#pragma unroll
        for (int i = 0; i < 2; i++) {
            int c4 = (tid & 3) + i * 4;         // 0..7
            cpa16(smem_u32(&Af[st * AF_STAGE + arow * AF_PITCH + c4 * 4]),
                  Asrc + (size_t)arow * 256 + c * 32 + c4 * 4);
        }
    };
    // B: 32k x 256n halves per chunk = 1024 x 16B; 2 per thread
    auto loadB = [&](const __half* Wp, int c, int st) {
#pragma unroll
        for (int i = 0; i < 2; i++) {
            int f = tid + i * 512;
            cpa16(smem_u32(&Bs[st * BS_STAGE + f * 8]),
                  Wp + (size_t)c * 8192 + f * 8);
        }
    };
    auto loadBfrags = [&](int st, int sl, uint32_t (*b)[2]) {
        const __half* bs = &Bs[st * BS_STAGE + sl * 4096 + wn * 1024];
#pragma unroll
        for (int j2 = 0; j2 < 4; j2++) {
            uint4 v = *(const uint4*)(bs + j2 * 256 + lane * 8);
            b[j2 * 2][0] = v.x;     b[j2 * 2][1] = v.y;
            b[j2 * 2 + 1][0] = v.z; b[j2 * 2 + 1][1] = v.w;
        }
    };

    // ================= phase 1: acc = X @ W1 =================
    loadA(0, 0); loadB(Wp1, 0, 0);
    asm volatile("cp.async.commit_group;" ::: "memory");
    loadA(1, 1); loadB(Wp1, 1, 1);
    asm volatile("cp.async.commit_group;" ::: "memory");
    loadA(2, 2); loadB(Wp1, 2, 2);
    asm volatile("cp.async.commit_group;" ::: "memory");

    // hidden under the cp.async fill: histogram + epilogue node prefetch
    if (tid < 128) atomicAdd(&cnt[ti[brow + tid]], 1);
    int nodes[2], nodes8[2];
#pragma unroll
    for (int mf = 0; mf < 2; mf++) {
        const int r = brow + wm * 32 + mf * 16 + gid;
        nodes[mf]  = ti[r];
        nodes8[mf] = ti[r + 8];
    }

    // groups: 0..7 = W1 chunks 0..7, 8..10 = W2 chunks 0..2.
    // at iter c: committed = 3+c, need group c  ->  wait_group 2 uniformly.
#pragma unroll
    for (int c = 0; c < 8; c++) {
        const int st = c & 3;
        asm volatile("cp.async.wait_group 2;" ::: "memory");
        __syncthreads();
        if (c + 3 < 8) {
            const int ls = (c + 3) & 3;                 // c=0..4
            loadA(c + 3, ls); loadB(Wp1, c + 3, ls);
            asm volatile("cp.async.commit_group;" ::: "memory");
        } else {
            // c=5,6,7: stage (c+3)&3 = 0,1,2 freed last iter -> W2 chunk c-5
            loadB(Wp2, c - 5, (c + 3) & 3);
            asm volatile("cp.async.commit_group;" ::: "memory");
        }
#pragma unroll
        for (int sl = 0; sl < 2; sl++) {
            const float* as = Af + st * AF_STAGE + wm * 32 * AF_PITCH + sl * 16;
            uint32_t a[2][4];
#pragma unroll
            for (int mf = 0; mf < 2; mf++) {
                const float* ar = as + (mf * 16 + gid) * AF_PITCH + tig * 2;
                float2 v0 = *(const float2*)(ar);
                float2 v1 = *(const float2*)(ar + 8 * AF_PITCH);
                float2 v2 = *(const float2*)(ar + 8);
                float2 v3 = *(const float2*)(ar + 8 * AF_PITCH + 8);
                a[mf][0] = h2(v0.x, v0.y);
                a[mf][1] = h2(v1.x, v1.y);
                a[mf][2] = h2(v2.x, v2.y);
                a[mf][3] = h2(v3.x, v3.y);
            }
            uint32_t b[8][2];
            loadBfrags(st, sl, b);
#pragma unroll
            for (int mf = 0; mf < 2; mf++)
#pragma unroll
                for (int j = 0; j < 8; j++)
                    mma_f16(acc[mf][j], a[mf], b[j]);
        }
    }

    // ---- phase 1 epilogue: relu(acc + b1) -> fp16 M1 tile ----
#pragma unroll
    for (int mf = 0; mf < 2; mf++) {
        const int r0 = wm * 32 + mf * 16 + gid, r1 = r0 + 8;
#pragma unroll
        for (int j = 0; j < 8; j++) {
            const int col = wn * 64 + j * 8 + tig * 2;
            float2 bv = *(const float2*)(b1 + col);
            *(uint32_t*)&M1[r0 * M1_PITCH + col] =
                h2(fmaxf(acc[mf][j][0] + bv.x, 0.f),
                   fmaxf(acc[mf][j][1] + bv.y, 0.f));
            *(uint32_t*)&M1[r1 * M1_PITCH + col] =
                h2(fmaxf(acc[mf][j][2] + bv.x, 0.f),
                   fmaxf(acc[mf][j][3] + bv.y, 0.f));
        }
    }

#pragma unroll
    for (int m = 0; m < 2; m++)
#pragma unroll
        for (int j = 0; j < 8; j++)
#pragma unroll
            for (int q = 0; q < 4; q++) acc[m][j][q] = 0.0f;

    // ================= phase 2: M1 @ W2, atomic scatter =================
    // W2 chunk k: k<=2 in stage k (groups 8..10, prefetched in phase 1);
    // k>=3 loaded below into stage k&3 (groups 11..15).
    const uint32_t m1base = smem_u32(
        &M1[(wm * 32 + (lane & 15)) * M1_PITCH + (lane >> 4) * 8]);

#pragma unroll
    for (int c = 0; c < 8; c++) {
        const int st = c & 3;
        if (c < 6)       asm volatile("cp.async.wait_group 2;" ::: "memory");
        else if (c == 6) asm volatile("cp.async.wait_group 1;" ::: "memory");
        else             asm volatile("cp.async.wait_group 0;" ::: "memory");
        __syncthreads();   // iter 0 also publishes M1 to all warps
        if (c + 3 < 8) {
            loadB(Wp2, c + 3, (c + 3) & 3);
            asm volatile("cp.async.commit_group;" ::: "memory");
        }
#pragma unroll
        for (int sl = 0; sl < 2; sl++) {
            uint32_t a[2][4];
#pragma unroll
            for (int mf = 0; mf < 2; mf++)
                ldmx4(a[mf], m1base +
                      (uint32_t)((mf * 16 * M1_PITCH + c * 32 + sl * 16) * 2));
            uint32_t b[8][2];
            loadBfrags(st, sl, b);
#pragma unroll
            for (int mf = 0; mf < 2; mf++)
#pragma unroll
                for (int j = 0; j < 8; j++)
                    mma_f16(acc[mf][j], a[mf], b[j]);
        }
    }

    // ---- phase 2 epilogue: relu(acc + b2), zero-skipped RED.v2 scatter ----
#pragma unroll
    for (int mf = 0; mf < 2; mf++) {
        float* p0 = out + (size_t)nodes[mf]  * 256 + wn * 64 + tig * 2;
        float* p1 = out + (size_t)nodes8[mf] * 256 + wn * 64 + tig * 2;
#pragma unroll
        for (int j = 0; j < 8; j++) {
            const int col = wn * 64 + j * 8 + tig * 2;
            float2 bv = *(const float2*)(b2 + col);
            float vx, vy;
            vx = fmaxf(acc[mf][j][0] + bv.x, 0.f);
            vy = fmaxf(acc[mf][j][1] + bv.y, 0.f);
            if (vx > 0.f || vy > 0.f) red_v2(p0 + j * 8, vx, vy);
            vx = fmaxf(acc[mf][j][2] + bv.x, 0.f);
            vy = fmaxf(acc[mf][j][3] + bv.y, 0.f);
            if (vx > 0.f || vy > 0.f) red_v2(p1 + j * 8, vx, vy);
        }
    }
}

// ------------------------------ kernel_launch -----------------------------

extern "C" void kernel_launch(void* const* d_in, const int* in_sizes, int n_in,
                              void* d_out, int out_size) {
    const float* X  = (const float*)d_in[0];
    const int*   ti = (const int*)d_in[1];
    int wi = 2;
    if (n_in >= 7 && in_sizes[2] <= 4) wi = 3;
    const float* W1 = (const float*)d_in[wi];
    const float* b1 = (const float*)d_in[wi + 1];
    const float* W2 = (const float*)d_in[wi + 2];
    const float* b2 = (const float*)d_in[wi + 3];

    const int E = in_sizes[1];        // 320000
    const int N = out_size / 256;     // 10000
    float* out = (float*)d_out;

    __half* wp0;  int* cnt;
    cudaGetSymbolAddress((void**)&wp0, g_wpack);
    cudaGetSymbolAddress((void**)&cnt, g_cnt);
    __half* wp1 = wp0 + 65536;

    cudaFuncSetAttribute(fused_mlp_kernel,
                         cudaFuncAttributeMaxDynamicSharedMemorySize,
                         (int)SHMEM_BYTES);

    const int n4 = out_size / 4;
    const int zblocks = (n4 + 255) / 256;
    prep_kernel<<<512 + zblocks, 256>>>(W1, W2, wp0, (float4*)out, n4, cnt, N);

    fused_mlp_kernel<<<E / 128, 512, SHMEM_BYTES>>>(X, wp0, wp1, b1, b2, out,
                                                    ti, cnt);
    finalize_kernel<<<(n4 + 255) / 256, 256>>>((float4*)out, cnt, n4);
}

// round 16
// speedup vs baseline: 1.2721x; 1.0037x over previous
#include <cuda_runtime.h>
#include <cuda_fp16.h>
#include <cstdint>

// ---------------------------------------------------------------------------
// HimpNetAlternative: out = scatter_mean( relu(relu(X@W1+b1)@W2+b2), to_index )
// E=320000, C=256, N=10000
//
// Round 16: R14 core untouched (GEMM at mma.sync pipe ceiling, 288.3us).
// Vectorized prep pack FIXED: 16384 threads total (8192/layer), layer split
// at t<8192, 64 pack blocks. (R15 launched 2x the threads and never selected
// W2 -> OOB writes + garbage layer-2 fragments.)
// ---------------------------------------------------------------------------

__device__ __half g_wpack[2][65536];   // W fragments, fp16
__device__ int    g_cnt[16384];

// ------------------------------- helpers ----------------------------------

__device__ __forceinline__ uint32_t smem_u32(const void* p) {
    uint32_t a;
    asm("{ .reg .u64 t; cvta.to.shared.u64 t, %1; cvt.u32.u64 %0, t; }"
        : "=r"(a) : "l"(p));
    return a;
}

__device__ __forceinline__ void cpa16(uint32_t s, const void* g) {
    asm volatile("cp.async.cg.shared.global [%0], [%1], 16;" :: "r"(s), "l"(g));
}

__device__ __forceinline__ void ldmx4(uint32_t* r, uint32_t addr) {
    asm volatile("ldmatrix.sync.aligned.m8n8.x4.shared.b16 {%0,%1,%2,%3}, [%4];"
                 : "=r"(r[0]), "=r"(r[1]), "=r"(r[2]), "=r"(r[3]) : "r"(addr));
}

__device__ __forceinline__ void mma_f16(float* d, const uint32_t* a,
                                        const uint32_t* b) {
    asm volatile(
        "mma.sync.aligned.m16n8k16.row.col.f32.f16.f16.f32 "
        "{%0,%1,%2,%3}, {%4,%5,%6,%7}, {%8,%9}, {%0,%1,%2,%3};"
        : "+f"(d[0]), "+f"(d[1]), "+f"(d[2]), "+f"(d[3])
        : "r"(a[0]), "r"(a[1]), "r"(a[2]), "r"(a[3]), "r"(b[0]), "r"(b[1]));
}

__device__ __forceinline__ uint32_t h2(float x, float y) {
    __half2 h = __floats2half2_rn(x, y);
    return *(uint32_t*)&h;
}

__device__ __forceinline__ void red_v2(float* p, float x, float y) {
    asm volatile("red.global.add.v2.f32 [%0], {%1, %2};"
                 :: "l"(p), "f"(x), "f"(y) : "memory");
}

// --------------------------------- prep -----------------------------------
// blocks [0,64): pack W1/W2 into fragment order, 8 halves per thread
//   (16384 threads total; threads [0,8192) pack W1, [8192,16384) pack W2).
// blocks [64, ...): zero out-sums + counts.
__global__ void prep_kernel(const float* __restrict__ Wa,
                            const float* __restrict__ Wb,
                            __half* __restrict__ dst,
                            float4* __restrict__ out, int n4,
                            int* __restrict__ cnt, int n_nodes) {
    int blk = blockIdx.x;
    if (blk < 64) {
        int t = blk * 256 + threadIdx.x;       // 16384 threads, 8192/layer
        const float* W = (t < 8192) ? Wa : Wb;
        int tl = t & 8191;                     // 8-half group index within layer
        // o = tl*8 + j ; o bits low->high: i(2), fp(1), lane(5), f2(3), nb(1), s(4)
        int lane = tl & 31;
        int f2   = (tl >> 5) & 7;
        int nb   = (tl >> 8) & 1;
        int s    = tl >> 9;                    // 0..15
        __half h[8];
#pragma unroll
        for (int j = 0; j < 8; j++) {
            int i = j & 3, fp = j >> 2;
            int f = f2 * 2 + fp;
            int n = nb * 128 + f * 8 + (lane >> 2);
            int k = s * 16 + (lane & 3) * 2 + (i & 1) + (i >> 1) * 8;
            h[j] = __float2half_rn(W[k * 256 + n]);
        }
        *(uint4*)(dst + (size_t)t * 8) = *(uint4*)h;
    } else {
        int i = (blk - 64) * 256 + threadIdx.x;
        if (i < n4)      out[i] = make_float4(0.f, 0.f, 0.f, 0.f);
        if (i < n_nodes) cnt[i] = 0;
    }
}

__global__ void finalize_kernel(float4* __restrict__ out,
                                const int* __restrict__ cnt, int n4) {
    int i = blockIdx.x * blockDim.x + threadIdx.x;
    if (i >= n4) return;
    int c = cnt[i >> 6];               // 64 float4 per 256-col row
    float4 v = out[i];
    if (c > 0) {
        float inv = 1.0f / (float)c;
        v.x *= inv; v.y *= inv; v.z *= inv; v.w *= inv;
    } else {
        v = make_float4(0.f, 0.f, 0.f, 0.f);
    }
    out[i] = v;
}

// ------------------------------ fused kernel -------------------------------
static constexpr int NSTAGE = 4;
static constexpr int AF_PITCH = 40;                   // floats (32 data + 8 pad)
static constexpr int AF_STAGE = 128 * AF_PITCH;       // 5120 floats
static constexpr int BS_STAGE = 8192;                 // halves (32k x 256n)
static constexpr int M1_PITCH = 264;                  // halves
static constexpr size_t SHMEM_BYTES =
    NSTAGE * AF_STAGE * 4 + NSTAGE * BS_STAGE * 2 + 128 * M1_PITCH * 2; // 215040

__global__ void __launch_bounds__(512, 1)
fused_mlp_kernel(const float* __restrict__ X,
                 const __half* __restrict__ Wp1, const __half* __restrict__ Wp2,
                 const float* __restrict__ b1, const float* __restrict__ b2,
                 float* __restrict__ out, const int* __restrict__ ti,
                 int* __restrict__ cnt) {
    extern __shared__ float smem[];
    float*  Af  = smem;
    __half* Bs  = (__half*)(smem + NSTAGE * AF_STAGE);
    __half* M1  = Bs + NSTAGE * BS_STAGE;

    const int tid  = threadIdx.x;
    const int lane = tid & 31, wid = tid >> 5;
    const int wm = wid & 3, wn = wid >> 2;       // 4M x 4N warps, tile 32x64
    const int gid = lane >> 2, tig = lane & 3;
    const int brow = blockIdx.x * 128;

    const float* Asrc = X + (size_t)brow * 256;

    float acc[2][8][4];
#pragma unroll
    for (int m = 0; m < 2; m++)
#pragma unroll
        for (int j = 0; j < 8; j++)
#pragma unroll
            for (int q = 0; q < 4; q++) acc[m][j][q] = 0.0f;

    // A: 128 rows x 32 floats per chunk = 1024 float4; 2 per thread
    const int arow = tid >> 2;

    auto loadA = [&](int c, int st) {
#pragma unroll
        for (int i = 0; i < 2; i++) {
            int c4 = (tid & 3) + i * 4;         // 0..7
            cpa16(smem_u32(&Af[st * AF_STAGE + arow * AF_PITCH + c4 * 4]),
                  Asrc + (size_t)arow * 256 + c * 32 + c4 * 4);
        }
    };
    // B: 32k x 256n halves per chunk = 1024 x 16B; 2 per thread
    auto loadB = [&](const __half* Wp, int c, int st) {
#pragma unroll
        for (int i = 0; i < 2; i++) {
            int f = tid + i * 512;
            cpa16(smem_u32(&Bs[st * BS_STAGE + f * 8]),
                  Wp + (size_t)c * 8192 + f * 8);
        }
    };
    auto loadBfrags = [&](int st, int sl, uint32_t (*b)[2]) {
        const __half* bs = &Bs[st * BS_STAGE + sl * 4096 + wn * 1024];
#pragma unroll
        for (int j2 = 0; j2 < 4; j2++) {
            uint4 v = *(const uint4*)(bs + j2 * 256 + lane * 8);
            b[j2 * 2][0] = v.x;     b[j2 * 2][1] = v.y;
            b[j2 * 2 + 1][0] = v.z; b[j2 * 2 + 1][1] = v.w;
        }
    };

    // ================= phase 1: acc = X @ W1 =================
    loadA(0, 0); loadB(Wp1, 0, 0);
    asm volatile("cp.async.commit_group;" ::: "memory");
    loadA(1, 1); loadB(Wp1, 1, 1);
    asm volatile("cp.async.commit_group;" ::: "memory");
    loadA(2, 2); loadB(Wp1, 2, 2);
    asm volatile("cp.async.commit_group;" ::: "memory");

    // hidden under the cp.async fill: histogram + epilogue node prefetch
    if (tid < 128) atomicAdd(&cnt[ti[brow + tid]], 1);
    int nodes[2], nodes8[2];
#pragma unroll
    for (int mf = 0; mf < 2; mf++) {
        const int r = brow + wm * 32 + mf * 16 + gid;
        nodes[mf]  = ti[r];
        nodes8[mf] = ti[r + 8];
    }

    // groups: 0..7 = W1 chunks 0..7, 8..10 = W2 chunks 0..2.
#pragma unroll
    for (int c = 0; c < 8; c++) {
        const int st = c & 3;
        asm volatile("cp.async.wait_group 2;" ::: "memory");
        __syncthreads();
        if (c + 3 < 8) {
            const int ls = (c + 3) & 3;                 // c=0..4
            loadA(c + 3, ls); loadB(Wp1, c + 3, ls);
            asm volatile("cp.async.commit_group;" ::: "memory");
        } else {
            // c=5,6,7: stage (c+3)&3 = 0,1,2 freed last iter -> W2 chunk c-5
            loadB(Wp2, c - 5, (c + 3) & 3);
            asm volatile("cp.async.commit_group;" ::: "memory");
        }
#pragma unroll
        for (int sl = 0; sl < 2; sl++) {
            const float* as = Af + st * AF_STAGE + wm * 32 * AF_PITCH + sl * 16;
            uint32_t a[2][4];
#pragma unroll
            for (int mf = 0; mf < 2; mf++) {
                const float* ar = as + (mf * 16 + gid) * AF_PITCH + tig * 2;
                float2 v0 = *(const float2*)(ar);
                float2 v1 = *(const float2*)(ar + 8 * AF_PITCH);
                float2 v2 = *(const float2*)(ar + 8);
                float2 v3 = *(const float2*)(ar + 8 * AF_PITCH + 8);
                a[mf][0] = h2(v0.x, v0.y);
                a[mf][1] = h2(v1.x, v1.y);
                a[mf][2] = h2(v2.x, v2.y);
                a[mf][3] = h2(v3.x, v3.y);
            }
            uint32_t b[8][2];
            loadBfrags(st, sl, b);
#pragma unroll
            for (int mf = 0; mf < 2; mf++)
#pragma unroll
                for (int j = 0; j < 8; j++)
                    mma_f16(acc[mf][j], a[mf], b[j]);
        }
    }

    // ---- phase 1 epilogue: relu(acc + b1) -> fp16 M1 tile ----
#pragma unroll
    for (int mf = 0; mf < 2; mf++) {
        const int r0 = wm * 32 + mf * 16 + gid, r1 = r0 + 8;
#pragma unroll
        for (int j = 0; j < 8; j++) {
            const int col = wn * 64 + j * 8 + tig * 2;
            float2 bv = *(const float2*)(b1 + col);
            *(uint32_t*)&M1[r0 * M1_PITCH + col] =
                h2(fmaxf(acc[mf][j][0] + bv.x, 0.f),
                   fmaxf(acc[mf][j][1] + bv.y, 0.f));
            *(uint32_t*)&M1[r1 * M1_PITCH + col] =
                h2(fmaxf(acc[mf][j][2] + bv.x, 0.f),
                   fmaxf(acc[mf][j][3] + bv.y, 0.f));
        }
    }

#pragma unroll
    for (int m = 0; m < 2; m++)
#pragma unroll
        for (int j = 0; j < 8; j++)
#pragma unroll
            for (int q = 0; q < 4; q++) acc[m][j][q] = 0.0f;

    // ================= phase 2: M1 @ W2, atomic scatter =================
    // W2 chunk k: k<=2 in stage k (groups 8..10, prefetched in phase 1);
    // k>=3 loaded below into stage k&3 (groups 11..15).
    const uint32_t m1base = smem_u32(
        &M1[(wm * 32 + (lane & 15)) * M1_PITCH + (lane >> 4) * 8]);

#pragma unroll
    for (int c = 0; c < 8; c++) {
        const int st = c & 3;
        if (c < 6)       asm volatile("cp.async.wait_group 2;" ::: "memory");
        else if (c == 6) asm volatile("cp.async.wait_group 1;" ::: "memory");
        else             asm volatile("cp.async.wait_group 0;" ::: "memory");
        __syncthreads();   // iter 0 also publishes M1 to all warps
        if (c + 3 < 8) {
            loadB(Wp2, c + 3, (c + 3) & 3);
            asm volatile("cp.async.commit_group;" ::: "memory");
        }
#pragma unroll
        for (int sl = 0; sl < 2; sl++) {
            uint32_t a[2][4];
#pragma unroll
            for (int mf = 0; mf < 2; mf++)
                ldmx4(a[mf], m1base +
                      (uint32_t)((mf * 16 * M1_PITCH + c * 32 + sl * 16) * 2));
            uint32_t b[8][2];
            loadBfrags(st, sl, b);
#pragma unroll
            for (int mf = 0; mf < 2; mf++)
#pragma unroll
                for (int j = 0; j < 8; j++)
                    mma_f16(acc[mf][j], a[mf], b[j]);
        }
    }

    // ---- phase 2 epilogue: relu(acc + b2), zero-skipped RED.v2 scatter ----
#pragma unroll
    for (int mf = 0; mf < 2; mf++) {
        float* p0 = out + (size_t)nodes[mf]  * 256 + wn * 64 + tig * 2;
        float* p1 = out + (size_t)nodes8[mf] * 256 + wn * 64 + tig * 2;
#pragma unroll
        for (int j = 0; j < 8; j++) {
            const int col = wn * 64 + j * 8 + tig * 2;
            float2 bv = *(const float2*)(b2 + col);
            float vx, vy;
            vx = fmaxf(acc[mf][j][0] + bv.x, 0.f);
            vy = fmaxf(acc[mf][j][1] + bv.y, 0.f);
            if (vx > 0.f || vy > 0.f) red_v2(p0 + j * 8, vx, vy);
            vx = fmaxf(acc[mf][j][2] + bv.x, 0.f);
            vy = fmaxf(acc[mf][j][3] + bv.y, 0.f);
            if (vx > 0.f || vy > 0.f) red_v2(p1 + j * 8, vx, vy);
        }
    }
}

// ------------------------------ kernel_launch -----------------------------

extern "C" void kernel_launch(void* const* d_in, const int* in_sizes, int n_in,
                              void* d_out, int out_size) {
    const float* X  = (const float*)d_in[0];
    const int*   ti = (const int*)d_in[1];
    int wi = 2;
    if (n_in >= 7 && in_sizes[2] <= 4) wi = 3;
    const float* W1 = (const float*)d_in[wi];
    const float* b1 = (const float*)d_in[wi + 1];
    const float* W2 = (const float*)d_in[wi + 2];
    const float* b2 = (const float*)d_in[wi + 3];

    const int E = in_sizes[1];        // 320000
    const int N = out_size / 256;     // 10000
    float* out = (float*)d_out;

    __half* wp0;  int* cnt;
    cudaGetSymbolAddress((void**)&wp0, g_wpack);
    cudaGetSymbolAddress((void**)&cnt, g_cnt);
    __half* wp1 = wp0 + 65536;

    cudaFuncSetAttribute(fused_mlp_kernel,
                         cudaFuncAttributeMaxDynamicSharedMemorySize,
                         (int)SHMEM_BYTES);

    const int n4 = out_size / 4;
    const int zblocks = (n4 + 255) / 256;
    prep_kernel<<<64 + zblocks, 256>>>(W1, W2, wp0, (float4*)out, n4, cnt, N);

    fused_mlp_kernel<<<E / 128, 512, SHMEM_BYTES>>>(X, wp0, wp1, b1, b2, out,
                                                    ti, cnt);
    finalize_kernel<<<(n4 + 255) / 256, 256>>>((float4*)out, cnt, n4);
}